// round 5
// baseline (speedup 1.0000x reference)
#include <cuda_runtime.h>

#define Bb 4
#define Qq 512
#define Kk 1024
#define VDd 256
#define Hh 128

#define TS 132          // scores tile stride (floats; /4 = 33 f4, 16B aligned)
#define AT2 68          // av attn smem stride

// Scratch (no allocations allowed).
__device__ __align__(16) float g_qp[Bb * Qq * Hh];   // 1 MB
__device__ __align__(16) float g_kp[Bb * Kk * Hh];   // 2 MB
__device__ __align__(16) float g_sc[Bb * Qq * Kk];   // 8 MB

__device__ __forceinline__ float tanh_fast(float x) {
    float y;
    asm("tanh.approx.f32 %0, %1;" : "=f"(y) : "f"(x));
    return y;
}

// ---------------------------------------------------------------------------
// Combined projection: g_qp = queries@W_q, g_kp = keys@W_k. 384 blocks.
// W chunk transposed in smem; d-loop vectorized by float4.
// ---------------------------------------------------------------------------
__global__ void __launch_bounds__(256)
proj_kernel(const float* __restrict__ queries,
            const float* __restrict__ W_q,
            const float* __restrict__ keys,
            const float* __restrict__ W_k) {
    __shared__ __align__(16) float a_s[16][260];   // stride 260 (f4 65)
    __shared__ __align__(16) float w_t[128][36];   // transposed W chunk

    const int bx = blockIdx.x;
    const float* A; const float* W; float* C; int row0;
    if (bx < (Bb * Qq) / 16) { A = queries; W = W_q; C = g_qp; row0 = bx * 16; }
    else { A = keys; W = W_k; C = g_kp; row0 = (bx - (Bb * Qq) / 16) * 16; }

    const int tid = threadIdx.x;

    // A tile 16x256 as float4.
    const float4* A4 = (const float4*)(A + (size_t)row0 * 256);
    #pragma unroll
    for (int i = 0; i < 4; i++) {
        int e = i * 256 + tid;               // f4 idx: row=e>>6, c4=e&63
        ((float4*)&a_s[e >> 6][0])[e & 63] = A4[e];
    }

    const int col = tid & 127;
    const int rg  = tid >> 7;
    float acc[8];
    #pragma unroll
    for (int i = 0; i < 8; i++) acc[i] = 0.f;

    for (int dc = 0; dc < 256; dc += 32) {
        __syncthreads();
        // W chunk 32x128 -> transposed w_t[c][r].
        #pragma unroll
        for (int i = 0; i < 16; i++) {
            int idx = i * 256 + tid;
            int r = idx >> 7, c = idx & 127;
            w_t[c][r] = W[(size_t)(dc + r) * 128 + c];
        }
        __syncthreads();
        const float4* wv4 = (const float4*)&w_t[col][0];
        #pragma unroll
        for (int d4 = 0; d4 < 8; d4++) {
            float4 wv = wv4[d4];
            #pragma unroll
            for (int i = 0; i < 8; i++) {
                float4 av = ((const float4*)&a_s[rg * 8 + i][dc])[d4];
                acc[i] += av.x * wv.x + av.y * wv.y + av.z * wv.z + av.w * wv.w;
            }
        }
    }
    __syncthreads();
    #pragma unroll
    for (int i = 0; i < 8; i++)
        C[(size_t)(row0 + rg * 8 + i) * 128 + col] = acc[i];
}

// ---------------------------------------------------------------------------
// Scores: 64q x 64k tile, 4x4 micro-tile, float4-vectorized over h.
// Masked tiles (k0 >= valid_len) exit immediately.
// ---------------------------------------------------------------------------
#define STEP(C)                                         \
    acc[0][0] += wv.C * tanh_fast(qv0.C + kv0.C);       \
    acc[0][1] += wv.C * tanh_fast(qv0.C + kv1.C);       \
    acc[0][2] += wv.C * tanh_fast(qv0.C + kv2.C);       \
    acc[0][3] += wv.C * tanh_fast(qv0.C + kv3.C);       \
    acc[1][0] += wv.C * tanh_fast(qv1.C + kv0.C);       \
    acc[1][1] += wv.C * tanh_fast(qv1.C + kv1.C);       \
    acc[1][2] += wv.C * tanh_fast(qv1.C + kv2.C);       \
    acc[1][3] += wv.C * tanh_fast(qv1.C + kv3.C);       \
    acc[2][0] += wv.C * tanh_fast(qv2.C + kv0.C);       \
    acc[2][1] += wv.C * tanh_fast(qv2.C + kv1.C);       \
    acc[2][2] += wv.C * tanh_fast(qv2.C + kv2.C);       \
    acc[2][3] += wv.C * tanh_fast(qv2.C + kv3.C);       \
    acc[3][0] += wv.C * tanh_fast(qv3.C + kv0.C);       \
    acc[3][1] += wv.C * tanh_fast(qv3.C + kv1.C);       \
    acc[3][2] += wv.C * tanh_fast(qv3.C + kv2.C);       \
    acc[3][3] += wv.C * tanh_fast(qv3.C + kv3.C);

__global__ void __launch_bounds__(256)
scores_kernel(const float* __restrict__ w_v,
              const int* __restrict__ valid_lens) {
    const int b  = blockIdx.z;
    const int k0 = blockIdx.x * 64;
    if (k0 >= valid_lens[b]) return;
    const int q0 = blockIdx.y * 64;

    extern __shared__ float sm[];
    float* qs = sm;                  // 64 * 132
    float* ks = qs + 64 * TS;        // 64 * 132
    float* ws = ks + 64 * TS;        // 128

    const int tid = threadIdx.x;

    const float4* qp4 = (const float4*)(g_qp + (size_t)(b * Qq + q0) * Hh);
    const float4* kp4 = (const float4*)(g_kp + (size_t)(b * Kk + k0) * Hh);
    #pragma unroll
    for (int i = 0; i < 8; i++) {
        int e = i * 256 + tid;               // f4 idx: row=e>>5, c4=e&31
        int r = e >> 5, c4 = e & 31;
        ((float4*)qs)[r * 33 + c4] = qp4[e];
        ((float4*)ks)[r * 33 + c4] = kp4[e];
    }
    if (tid < 32) ((float4*)ws)[tid] = ((const float4*)w_v)[tid];
    __syncthreads();

    const int tx = tid & 15;
    const int ty = tid >> 4;
    const float4* qb4 = (const float4*)qs + (4 * ty) * 33;
    const float4* kb4 = (const float4*)ks + (4 * tx) * 33;
    const float4* ws4 = (const float4*)ws;

    float acc[4][4];
    #pragma unroll
    for (int i = 0; i < 4; i++)
        #pragma unroll
        for (int j = 0; j < 4; j++) acc[i][j] = 0.f;

    for (int h4 = 0; h4 < 32; h4++) {
        float4 wv  = ws4[h4];
        float4 qv0 = qb4[h4], qv1 = qb4[33 + h4];
        float4 qv2 = qb4[66 + h4], qv3 = qb4[99 + h4];
        float4 kv0 = kb4[h4], kv1 = kb4[33 + h4];
        float4 kv2 = kb4[66 + h4], kv3 = kb4[99 + h4];
        STEP(x)
        STEP(y)
        STEP(z)
        STEP(w)
    }

    #pragma unroll
    for (int i = 0; i < 4; i++) {
        float4 r = make_float4(acc[i][0], acc[i][1], acc[i][2], acc[i][3]);
        *(float4*)&g_sc[(size_t)(b * Qq + q0 + 4 * ty + i) * Kk + k0 + 4 * tx] = r;
    }
}

// ---------------------------------------------------------------------------
// Softmax over k < valid_len; writes EXACT zeros beyond (AV relies on this).
// ---------------------------------------------------------------------------
__global__ void softmax_kernel(const int* __restrict__ valid_lens) {
    const int row = blockIdx.x;
    const int b   = row >> 9;
    const int vl  = valid_lens[b];
    const int tid = threadIdx.x;
    const float NINF = __int_as_float(0xff800000);

    float4* p = (float4*)&g_sc[(size_t)row * Kk];
    float4 v = p[tid];
    const int k = 4 * tid;
    float e0 = (k     < vl) ? v.x : NINF;
    float e1 = (k + 1 < vl) ? v.y : NINF;
    float e2 = (k + 2 < vl) ? v.z : NINF;
    float e3 = (k + 3 < vl) ? v.w : NINF;

    __shared__ float redm[8];
    __shared__ float reds[8];
    const int wid = tid >> 5, lid = tid & 31;

    float m = fmaxf(fmaxf(e0, e1), fmaxf(e2, e3));
    #pragma unroll
    for (int o = 16; o; o >>= 1) m = fmaxf(m, __shfl_xor_sync(~0u, m, o));
    if (lid == 0) redm[wid] = m;
    __syncthreads();
    m = redm[0];
    #pragma unroll
    for (int i = 1; i < 8; i++) m = fmaxf(m, redm[i]);

    float p0 = (k     < vl) ? __expf(e0 - m) : 0.f;
    float p1 = (k + 1 < vl) ? __expf(e1 - m) : 0.f;
    float p2 = (k + 2 < vl) ? __expf(e2 - m) : 0.f;
    float p3 = (k + 3 < vl) ? __expf(e3 - m) : 0.f;

    float s = p0 + p1 + p2 + p3;
    #pragma unroll
    for (int o = 16; o; o >>= 1) s += __shfl_xor_sync(~0u, s, o);
    if (lid == 0) reds[wid] = s;
    __syncthreads();
    s = reds[0];
    #pragma unroll
    for (int i = 1; i < 8; i++) s += reds[i];

    float inv = __frcp_rn(s);
    p[tid] = make_float4(p0 * inv, p1 * inv, p2 * inv, p3 * inv);
}

// ---------------------------------------------------------------------------
// AV: out = attn @ values. Tile 32q x 64v, 256 threads, 2q x 4v per thread,
// k-chunk 64, register double-buffered. Grid (VD/64, Q/32, B) = 256 blocks.
// ---------------------------------------------------------------------------
__global__ void __launch_bounds__(256)
av_kernel(const float* __restrict__ values,
          const int* __restrict__ valid_lens,
          float* __restrict__ out) {
    __shared__ __align__(16) float at_s[32 * AT2];   // 8.7 KB
    __shared__ __align__(16) float vs_s[64 * 64];    // 16 KB

    const int b   = blockIdx.z;
    const int q0  = blockIdx.y * 32;
    const int v0  = blockIdx.x * 64;
    const int tid = threadIdx.x;
    const int tx  = tid & 15;        // 4 v cols: 4*tx
    const int ty  = tid >> 4;        // 2 q rows: 2*ty, 2*ty+1
    const int vl  = valid_lens[b];

    const float* attn = g_sc + (size_t)(b * Qq + q0) * Kk;
    const float* vals = values + (size_t)b * Kk * VDd + v0;

    // attn tile: 32 rows x 16 f4 = 512 f4, 2/thread.
    const int ar0 = tid >> 4,          ac0 = tid & 15;
    const int ar1 = (tid + 256) >> 4,  ac1 = ac0;
    // values tile: 64 rows x 16 f4 = 1024 f4, 4/thread.
    const int vr0 = ar0, vr1 = ar1;
    const int vr2 = (tid + 512) >> 4, vr3 = (tid + 768) >> 4;

    float4 pa0, pa1, pv0, pv1, pv2, pv3;
    pa0 = ((const float4*)(attn + (size_t)ar0 * Kk))[ac0];
    pa1 = ((const float4*)(attn + (size_t)ar1 * Kk))[ac1];
    pv0 = ((const float4*)(vals + (size_t)vr0 * VDd))[ac0];
    pv1 = ((const float4*)(vals + (size_t)vr1 * VDd))[ac0];
    pv2 = ((const float4*)(vals + (size_t)vr2 * VDd))[ac0];
    pv3 = ((const float4*)(vals + (size_t)vr3 * VDd))[ac0];

    float4 acc0 = make_float4(0.f, 0.f, 0.f, 0.f);
    float4 acc1 = acc0;

    const int nchunk = (vl + 63) >> 6;
    for (int c = 0; c < nchunk; c++) {
        ((float4*)(at_s + ar0 * AT2))[ac0] = pa0;
        ((float4*)(at_s + ar1 * AT2))[ac1] = pa1;
        ((float4*)vs_s)[vr0 * 16 + ac0] = pv0;
        ((float4*)vs_s)[vr1 * 16 + ac0] = pv1;
        ((float4*)vs_s)[vr2 * 16 + ac0] = pv2;
        ((float4*)vs_s)[vr3 * 16 + ac0] = pv3;
        __syncthreads();

        if (c + 1 < nchunk) {
            const float* an = attn + (c + 1) * 64;
            const float* vn = vals + (size_t)(c + 1) * 64 * VDd;
            pa0 = ((const float4*)(an + (size_t)ar0 * Kk))[ac0];
            pa1 = ((const float4*)(an + (size_t)ar1 * Kk))[ac1];
            pv0 = ((const float4*)(vn + (size_t)vr0 * VDd))[ac0];
            pv1 = ((const float4*)(vn + (size_t)vr1 * VDd))[ac0];
            pv2 = ((const float4*)(vn + (size_t)vr2 * VDd))[ac0];
            pv3 = ((const float4*)(vn + (size_t)vr3 * VDd))[ac0];
        }

        const float* a0 = at_s + (2 * ty) * AT2;
        const float* a1 = a0 + AT2;
        const float4* vrow = (const float4*)vs_s + tx;
        #pragma unroll 16
        for (int k = 0; k < 64; k++) {
            float w0 = a0[k], w1 = a1[k];
            float4 vv = vrow[k * 16];
            acc0.x += w0 * vv.x; acc0.y += w0 * vv.y;
            acc0.z += w0 * vv.z; acc0.w += w0 * vv.w;
            acc1.x += w1 * vv.x; acc1.y += w1 * vv.y;
            acc1.z += w1 * vv.z; acc1.w += w1 * vv.w;
        }
        __syncthreads();
    }

    float4* o0 = (float4*)(out + (size_t)(b * Qq + q0 + 2 * ty) * VDd + v0);
    float4* o1 = (float4*)(out + (size_t)(b * Qq + q0 + 2 * ty + 1) * VDd + v0);
    o0[tx] = acc0;
    o1[tx] = acc1;
}

// ---------------------------------------------------------------------------
extern "C" void kernel_launch(void* const* d_in, const int* in_sizes, int n_in,
                              void* d_out, int out_size) {
    const float* queries    = (const float*)d_in[0];
    const float* keys       = (const float*)d_in[1];
    const float* values     = (const float*)d_in[2];
    const int*   valid_lens = (const int*)  d_in[3];
    const float* W_q        = (const float*)d_in[4];
    const float* W_k        = (const float*)d_in[5];
    const float* w_v        = (const float*)d_in[6];
    float* out = (float*)d_out;

    proj_kernel<<<(Bb * Qq) / 16 + (Bb * Kk) / 16, 256>>>(queries, W_q, keys, W_k);

    const int sc_smem = (64 * TS * 2 + Hh) * (int)sizeof(float);
    cudaFuncSetAttribute(scores_kernel, cudaFuncAttributeMaxDynamicSharedMemorySize,
                         sc_smem);
    scores_kernel<<<dim3(Kk / 64, Qq / 64, Bb), 256, sc_smem>>>(w_v, valid_lens);

    softmax_kernel<<<Bb * Qq, 256>>>(valid_lens);

    av_kernel<<<dim3(VDd / 64, Qq / 32, Bb), 256>>>(values, valid_lens, out);
}